// round 2
// baseline (speedup 1.0000x reference)
#include <cuda_runtime.h>
#include <cuda_bf16.h>
#include <math_constants.h>
#include <cstdint>

// Problem constants
#define B_   4
#define T_   256
#define U_   64
#define DK_  512      // D_ENC == D_DEC
#define F_   1024     // IN_F
#define V_   1024
#define ROWS_ (B_*T_*U_)   // 65536

// Scratch (static __device__ arrays: the sanctioned no-alloc workaround)
__device__ float g_pe[B_*T_*F_];                 // [1024, 1024]  4 MB
__device__ float g_pd[B_*U_*F_];                 // [256, 1024]   1 MB
__device__ float g_logits[(size_t)ROWS_ * V_];   // [65536, 1024] 256 MB

// Fast tanh: tanh(x) = 1 - 2/(exp(2x)+1). Safe at +/-inf (returns +/-1).
__device__ __forceinline__ float ftanh(float x) {
    float e = __expf(2.0f * x);
    return 1.0f - __fdividef(2.0f, e + 1.0f);
}

// ---------------------------------------------------------------------------
// Projection GEMM: Y[M,1024] = X[M,512] @ W[512,1024] + bias
// which==0 -> g_pe, which==1 -> g_pd
// Block: 64x64 tile, BK=16, 256 threads, 4x4 microtile.
// ---------------------------------------------------------------------------
__global__ void __launch_bounds__(256) proj_kernel(
    const float* __restrict__ X, const float* __restrict__ W,
    const float* __restrict__ bias, int which)
{
    __shared__ float Xs[16][64];
    __shared__ float Ws[16][64];

    float* __restrict__ Y = (which == 0) ? g_pe : g_pd;

    const int t  = threadIdx.x;
    const int n0 = blockIdx.x * 64;
    const int m0 = blockIdx.y * 64;
    const int tx = t & 15;
    const int ty = t >> 4;

    // X-load mapping: each thread loads float4 along k for one m
    const int xm = t & 63;        // 0..63
    const int xq = t >> 6;        // 0..3  -> k offset xq*4
    // W-load mapping: coalesced float4
    const int wk = t >> 4;        // 0..15
    const int wn = (t & 15) * 4;  // 0..60

    float acc[4][4] = {};

    for (int k0 = 0; k0 < DK_; k0 += 16) {
        float4 xv = *(const float4*)&X[(size_t)(m0 + xm) * DK_ + k0 + xq * 4];
        Xs[xq*4+0][xm] = xv.x;
        Xs[xq*4+1][xm] = xv.y;
        Xs[xq*4+2][xm] = xv.z;
        Xs[xq*4+3][xm] = xv.w;
        *(float4*)&Ws[wk][wn] = *(const float4*)&W[(size_t)(k0 + wk) * F_ + n0 + wn];
        __syncthreads();

        #pragma unroll
        for (int kk = 0; kk < 16; kk++) {
            float4 av = *(float4*)&Xs[kk][ty*4];
            float4 bv = *(float4*)&Ws[kk][tx*4];
            float a[4] = {av.x, av.y, av.z, av.w};
            float b[4] = {bv.x, bv.y, bv.z, bv.w};
            #pragma unroll
            for (int i = 0; i < 4; i++)
                #pragma unroll
                for (int j = 0; j < 4; j++)
                    acc[i][j] += a[i] * b[j];
        }
        __syncthreads();
    }

    float4 bb = *(const float4*)&bias[n0 + tx*4];
    #pragma unroll
    for (int i = 0; i < 4; i++) {
        float4 o;
        o.x = acc[i][0] + bb.x;
        o.y = acc[i][1] + bb.y;
        o.z = acc[i][2] + bb.z;
        o.w = acc[i][3] + bb.w;
        *(float4*)&Y[(size_t)(m0 + ty*4 + i) * F_ + n0 + tx*4] = o;
    }
}

// ---------------------------------------------------------------------------
// Main GEMM: logits[r, v] = sum_k tanh(pe[r/64, k] + pd[pdrow(r), k]) * W_fc[k, v]
// r = ((b*T + t)*U + u); pe row = r/64 (= b*T+t); pd row = (r>>14)*64 + (r&63).
// 128x128 tile, BK=16, 256 threads, 8x8 microtile with split fragments
// (cols {tx*4, 64+tx*4}, rows {ty*4, 64+ty*4}) -> conflict-free LDS.128.
// ---------------------------------------------------------------------------
__global__ void __launch_bounds__(256, 2) joint_gemm(const float* __restrict__ Wfc)
{
    __shared__ float As[16][128];
    __shared__ float Bs[16][128];

    const int t    = threadIdx.x;
    const int n0   = blockIdx.x * 128;
    const int row0 = blockIdx.y * 128;
    const int tx   = t & 15;
    const int ty   = t >> 4;

    // A-load mapping: 128 rows x 16 k; threads 0-127 take k 0..7, 128-255 take k 8..15
    const int am = t & 127;
    const int ah = (t >> 7) * 8;       // 0 or 8
    const int r  = row0 + am;
    const int pe_row = r >> 6;                         // b*T + t
    const int pd_row = ((r >> 14) << 6) | (r & 63);    // b*U + u
    const float* peP = g_pe + (size_t)pe_row * F_ + ah;
    const float* pdP = g_pd + (size_t)pd_row * F_ + ah;

    float acc[8][8] = {};

    for (int k0 = 0; k0 < F_; k0 += 16) {
        // A tile (on-the-fly tanh)
        float4 p0 = *(const float4*)(peP + k0);
        float4 p1 = *(const float4*)(peP + k0 + 4);
        float4 q0 = *(const float4*)(pdP + k0);
        float4 q1 = *(const float4*)(pdP + k0 + 4);
        As[ah+0][am] = ftanh(p0.x + q0.x);
        As[ah+1][am] = ftanh(p0.y + q0.y);
        As[ah+2][am] = ftanh(p0.z + q0.z);
        As[ah+3][am] = ftanh(p0.w + q0.w);
        As[ah+4][am] = ftanh(p1.x + q1.x);
        As[ah+5][am] = ftanh(p1.y + q1.y);
        As[ah+6][am] = ftanh(p1.z + q1.z);
        As[ah+7][am] = ftanh(p1.w + q1.w);

        // B tile: 16 x 128 = 512 float4s, 2 per thread, coalesced
        {
            int e = t;
            int k = e >> 5, c = (e & 31) * 4;
            *(float4*)&Bs[k][c] = *(const float4*)&Wfc[(size_t)(k0 + k) * V_ + n0 + c];
            e = t + 256;
            k = e >> 5; c = (e & 31) * 4;
            *(float4*)&Bs[k][c] = *(const float4*)&Wfc[(size_t)(k0 + k) * V_ + n0 + c];
        }
        __syncthreads();

        #pragma unroll
        for (int kk = 0; kk < 16; kk++) {
            float a[8], b[8];
            *(float4*)&a[0] = *(float4*)&As[kk][ty*4];
            *(float4*)&a[4] = *(float4*)&As[kk][64 + ty*4];
            *(float4*)&b[0] = *(float4*)&Bs[kk][tx*4];
            *(float4*)&b[4] = *(float4*)&Bs[kk][64 + tx*4];
            #pragma unroll
            for (int i = 0; i < 8; i++)
                #pragma unroll
                for (int j = 0; j < 8; j++)
                    acc[i][j] += a[i] * b[j];
        }
        __syncthreads();
    }

    // Epilogue: rows {row0+ty*4+i, row0+64+ty*4+i}, cols {n0+tx*4, n0+64+tx*4}
    #pragma unroll
    for (int ih = 0; ih < 2; ih++) {
        #pragma unroll
        for (int i = 0; i < 4; i++) {
            const int rr = row0 + ih*64 + ty*4 + i;
            float* o = g_logits + (size_t)rr * V_ + n0;
            float4 v0, v1;
            v0.x = acc[ih*4+i][0]; v0.y = acc[ih*4+i][1];
            v0.z = acc[ih*4+i][2]; v0.w = acc[ih*4+i][3];
            v1.x = acc[ih*4+i][4]; v1.y = acc[ih*4+i][5];
            v1.z = acc[ih*4+i][6]; v1.w = acc[ih*4+i][7];
            *(float4*)(o + tx*4)      = v0;
            *(float4*)(o + 64 + tx*4) = v1;
        }
    }
}

// ---------------------------------------------------------------------------
// Bias + log-softmax + mask. One warp per row (V=1024 -> 32 floats/thread).
// Masked rows written as exact 0.0 (matches jnp.where(..., 0.0)).
// ---------------------------------------------------------------------------
__global__ void __launch_bounds__(256) softmax_mask_kernel(
    const float* __restrict__ bfc,
    const int* __restrict__ enc_lens, const int* __restrict__ dec_lens,
    float* __restrict__ out)
{
    __shared__ float sb[V_];
    for (int i = threadIdx.x; i < V_; i += 256) sb[i] = bfc[i];
    __syncthreads();

    const int warp = threadIdx.x >> 5;
    const int lane = threadIdx.x & 31;
    const int row  = blockIdx.x * 8 + warp;   // 8192 blocks * 8 warps = 65536 rows

    const int b  = row >> 14;             // / (T*U)
    const int tt = (row >> 6) & (T_ - 1); // t
    const int u  = row & (U_ - 1);        // u

    const float4* lrow = (const float4*)(g_logits + (size_t)row * V_);
    float4*       orow = (float4*)(out + (size_t)row * V_);

    const bool ok = (tt < enc_lens[b]) && (u < dec_lens[b]);
    if (!ok) {
        float4 z = make_float4(0.f, 0.f, 0.f, 0.f);
        #pragma unroll
        for (int j = 0; j < 8; j++) orow[j*32 + lane] = z;
        return;
    }

    float v[32];
    float mx = -CUDART_INF_F;
    #pragma unroll
    for (int j = 0; j < 8; j++) {
        float4 x  = lrow[j*32 + lane];
        float4 bb = ((const float4*)sb)[j*32 + lane];
        x.x += bb.x; x.y += bb.y; x.z += bb.z; x.w += bb.w;
        v[j*4+0] = x.x; v[j*4+1] = x.y; v[j*4+2] = x.z; v[j*4+3] = x.w;
        mx = fmaxf(mx, fmaxf(fmaxf(x.x, x.y), fmaxf(x.z, x.w)));
    }
    #pragma unroll
    for (int o = 16; o > 0; o >>= 1)
        mx = fmaxf(mx, __shfl_xor_sync(0xFFFFFFFFu, mx, o));

    float s = 0.f;
    #pragma unroll
    for (int i = 0; i < 32; i++) s += __expf(v[i] - mx);
    #pragma unroll
    for (int o = 16; o > 0; o >>= 1)
        s += __shfl_xor_sync(0xFFFFFFFFu, s, o);

    const float lse = mx + logf(s);

    #pragma unroll
    for (int j = 0; j < 8; j++) {
        float4 y;
        y.x = v[j*4+0] - lse; y.y = v[j*4+1] - lse;
        y.z = v[j*4+2] - lse; y.w = v[j*4+3] - lse;
        orow[j*32 + lane] = y;
    }
}

// ---------------------------------------------------------------------------
extern "C" void kernel_launch(void* const* d_in, const int* in_sizes, int n_in,
                              void* d_out, int out_size)
{
    const float* enc      = (const float*)d_in[0];
    const float* dec      = (const float*)d_in[1];
    const float* W_enc    = (const float*)d_in[2];
    const float* b_enc    = (const float*)d_in[3];
    const float* W_dec    = (const float*)d_in[4];
    const float* b_dec    = (const float*)d_in[5];
    const float* W_fc     = (const float*)d_in[6];
    const float* b_fc     = (const float*)d_in[7];
    const int*   enc_lens = (const int*)d_in[8];
    const int*   dec_lens = (const int*)d_in[9];
    float* out = (float*)d_out;
    (void)in_sizes; (void)n_in; (void)out_size;

    // pe = enc @ W_enc + b_enc   (M = B*T = 1024)
    proj_kernel<<<dim3(F_/64, (B_*T_)/64), 256>>>(enc, W_enc, b_enc, 0);
    // pd = dec @ W_dec + b_dec   (M = B*U = 256)
    proj_kernel<<<dim3(F_/64, (B_*U_)/64), 256>>>(dec, W_dec, b_dec, 1);
    // logits = tanh(pe (+) pd) @ W_fc
    joint_gemm<<<dim3(V_/128, ROWS_/128), 256>>>(W_fc);
    // out = log_softmax(logits + b_fc) with length masking
    softmax_mask_kernel<<<ROWS_/8, 256>>>(b_fc, enc_lens, dec_lens, out);
}

// round 4
// speedup vs baseline: 5.6275x; 5.6275x over previous
#include <cuda_runtime.h>
#include <cuda_bf16.h>
#include <math_constants.h>
#include <cstdint>

// Problem constants
#define B_   4
#define T_   256
#define U_   64
#define DK_  512      // D_ENC == D_DEC
#define F_   1024     // IN_F
#define V_   1024
#define ROWS_ (B_*T_*U_)   // 65536

// Scratch (static __device__ arrays: the sanctioned no-alloc workaround)
__device__ float g_pe[B_*T_*F_];                          // 4 MB
__device__ float g_pd[B_*U_*F_];                          // 1 MB
__device__ __nv_bfloat16 g_A[(size_t)ROWS_ * F_];         // 128 MB  bf16 tanh grid
__device__ __nv_bfloat16 g_WT[(size_t)V_ * F_];           // 2 MB    Wfc^T bf16, K-major
__device__ float g_logits[(size_t)ROWS_ * V_];            // 256 MB

__device__ __forceinline__ uint32_t smem_u32(const void* p) {
    uint32_t a;
    asm("{ .reg .u64 t; cvta.to.shared.u64 t, %1; cvt.u32.u64 %0, t; }" : "=r"(a) : "l"(p));
    return a;
}

// ---------------------------------------------------------------------------
// FMA-pipe-only tanh (MUFU-free): Eigen rational minimax + magic reciprocal
// ---------------------------------------------------------------------------
__device__ __forceinline__ float ftanh(float x) {
    x = fmaxf(-7.90531110763549805f, fminf(7.90531110763549805f, x));
    float x2 = x * x;
    float p = fmaf(x2, -2.76076847742355e-16f, 2.00018790482477e-13f);
    p = fmaf(p, x2, -8.60467152213735e-11f);
    p = fmaf(p, x2,  5.12229709037114e-08f);
    p = fmaf(p, x2,  1.48572235717979e-05f);
    p = fmaf(p, x2,  6.37261928875436e-04f);
    p = fmaf(p, x2,  4.89352455891786e-03f);
    p = p * x;
    float q = fmaf(x2, 1.19825839466702e-06f, 1.18534705686654e-04f);
    q = fmaf(q, x2, 2.26843463243900e-03f);
    q = fmaf(q, x2, 4.89352518554385e-03f);
    float r = __int_as_float(0x7EF311C3 - __float_as_int(q));
    r = r * fmaf(-q, r, 2.0f);
    r = r * fmaf(-q, r, 2.0f);
    return p * r;
}

__device__ __forceinline__ uint32_t pack_bf16x2(float lo, float hi) {
    uint32_t r;
    asm("cvt.rn.bf16x2.f32 %0, %1, %2;" : "=r"(r) : "f"(hi), "f"(lo));
    return r;
}

// ---------------------------------------------------------------------------
// Projection GEMM: Y[M,1024] = X[M,512] @ W + bias   (validated in R1)
// ---------------------------------------------------------------------------
__global__ void __launch_bounds__(256) proj_kernel(
    const float* __restrict__ X, const float* __restrict__ W,
    const float* __restrict__ bias, int which)
{
    __shared__ float Xs[16][64];
    __shared__ float Ws[16][64];
    float* __restrict__ Y = (which == 0) ? g_pe : g_pd;

    const int t  = threadIdx.x;
    const int n0 = blockIdx.x * 64;
    const int m0 = blockIdx.y * 64;
    const int tx = t & 15;
    const int ty = t >> 4;
    const int xm = t & 63;
    const int xq = t >> 6;
    const int wk = t >> 4;
    const int wn = (t & 15) * 4;

    float acc[4][4] = {};
    for (int k0 = 0; k0 < DK_; k0 += 16) {
        float4 xv = *(const float4*)&X[(size_t)(m0 + xm) * DK_ + k0 + xq * 4];
        Xs[xq*4+0][xm] = xv.x; Xs[xq*4+1][xm] = xv.y;
        Xs[xq*4+2][xm] = xv.z; Xs[xq*4+3][xm] = xv.w;
        *(float4*)&Ws[wk][wn] = *(const float4*)&W[(size_t)(k0 + wk) * F_ + n0 + wn];
        __syncthreads();
        #pragma unroll
        for (int kk = 0; kk < 16; kk++) {
            float4 av = *(float4*)&Xs[kk][ty*4];
            float4 bv = *(float4*)&Ws[kk][tx*4];
            float a[4] = {av.x, av.y, av.z, av.w};
            float b[4] = {bv.x, bv.y, bv.z, bv.w};
            #pragma unroll
            for (int i = 0; i < 4; i++)
                #pragma unroll
                for (int j = 0; j < 4; j++)
                    acc[i][j] += a[i] * b[j];
        }
        __syncthreads();
    }
    float4 bb = *(const float4*)&bias[n0 + tx*4];
    #pragma unroll
    for (int i = 0; i < 4; i++) {
        float4 o;
        o.x = acc[i][0] + bb.x; o.y = acc[i][1] + bb.y;
        o.z = acc[i][2] + bb.z; o.w = acc[i][3] + bb.w;
        *(float4*)&Y[(size_t)(m0 + ty*4 + i) * F_ + n0 + tx*4] = o;
    }
}

// ---------------------------------------------------------------------------
// Wfc transpose + fp32->bf16: g_WT[v][k] = bf16(W_fc[k][v])
// ---------------------------------------------------------------------------
__global__ void __launch_bounds__(256) transpose_w(const float* __restrict__ W)
{
    __shared__ float tile[32][33];
    const int x0 = blockIdx.x * 32;   // v
    const int y0 = blockIdx.y * 32;   // k
    const int tx = threadIdx.x & 31;
    const int ty = threadIdx.x >> 5;  // 0..7
    #pragma unroll
    for (int i = 0; i < 32; i += 8)
        tile[ty + i][tx] = W[(size_t)(y0 + ty + i) * V_ + x0 + tx];
    __syncthreads();
    #pragma unroll
    for (int i = 0; i < 32; i += 8)
        g_WT[(size_t)(x0 + ty + i) * F_ + y0 + tx] = __float2bfloat16(tile[tx][ty + i]);
}

// ---------------------------------------------------------------------------
// A-build: g_A[r][k] = bf16(tanh(pe[r>>6][k] + pd[(r>>14)*64 + (r&63)][k]))
// ---------------------------------------------------------------------------
__global__ void __launch_bounds__(256) build_A()
{
    __shared__ float pes[F_];
    const int bt = blockIdx.x;          // b*T + t
    const int b  = bt >> 8;             // / T_
    const float* per = g_pe + (size_t)bt * F_;
    for (int i = threadIdx.x; i < F_ / 4; i += 256)
        ((float4*)pes)[i] = ((const float4*)per)[i];
    __syncthreads();

    const int k8 = (threadIdx.x & 127) * 8;
    const int uo = threadIdx.x >> 7;    // 0 or 1
    const float* pdb = g_pd + (size_t)(b * U_) * F_;
    __nv_bfloat16* arow = g_A + (size_t)bt * U_ * F_;

    const float4 p0 = *(const float4*)(pes + k8);
    const float4 p1 = *(const float4*)(pes + k8 + 4);

    for (int us = 0; us < U_; us += 2) {
        const int u = us + uo;
        const float* pdr = pdb + (size_t)u * F_ + k8;
        float4 q0 = *(const float4*)pdr;
        float4 q1 = *(const float4*)(pdr + 4);
        uint4 o;
        o.x = pack_bf16x2(ftanh(p0.x + q0.x), ftanh(p0.y + q0.y));
        o.y = pack_bf16x2(ftanh(p0.z + q0.z), ftanh(p0.w + q0.w));
        o.z = pack_bf16x2(ftanh(p1.x + q1.x), ftanh(p1.y + q1.y));
        o.w = pack_bf16x2(ftanh(p1.z + q1.z), ftanh(p1.w + q1.w));
        *(uint4*)(arow + (size_t)u * F_ + k8) = o;
    }
}

// ---------------------------------------------------------------------------
// Main GEMM via mma.sync (base sm_100 target; tcgen05 not assemblable here).
// CTA 128x128, K-chunk 64, 3-stage cp.async pipeline, SW128 swizzle.
// 8 warps in 2(M)x4(N) grid; warp tile 64x32 = 4x4 m16n8k16 accumulators.
// ---------------------------------------------------------------------------
#define KCH    64
#define NSTG   3
#define STG_B  32768          // 16KB A + 16KB B per stage
#define SMEM_GEMM (NSTG * STG_B)   // 96 KB

__global__ void __launch_bounds__(256, 2) joint_gemm_mma()
{
    extern __shared__ char smem[];
    const uint32_t sb = smem_u32(smem);
    const int tid = threadIdx.x;
    const int n0   = blockIdx.x * 128;
    const int row0 = blockIdx.y * 128;
    const int w  = tid >> 5, l = tid & 31;
    const int wm = w & 1,  wn = w >> 1;

    const __nv_bfloat16* Abase = g_A  + (size_t)row0 * F_;
    const __nv_bfloat16* Bbase = g_WT + (size_t)n0   * F_;

    // cp.async load mapping: thread -> (row lr, 16B-unit lu); 4 rows-strides each
    const int lr = tid >> 3;   // 0..31
    const int lu = tid & 7;    // 0..7 (unit of 16B within 128B row)
    const int lsw = lu ^ (lr & 7);   // swizzled unit (row stride 32 keeps lr&7)

    auto load_stage = [&](int s, int k0) {
        const uint32_t as_ = sb + (uint32_t)s * STG_B;
        const uint32_t bs_ = as_ + 16384;
        #pragma unroll
        for (int i = 0; i < 4; i++) {
            const int r = lr + i * 32;
            const uint32_t d = as_ + r * 128 + lsw * 16;
            const void* g = Abase + (size_t)r * F_ + k0 + lu * 8;
            asm volatile("cp.async.cg.shared.global [%0], [%1], 16;" :: "r"(d), "l"(g));
        }
        #pragma unroll
        for (int i = 0; i < 4; i++) {
            const int r = lr + i * 32;
            const uint32_t d = bs_ + r * 128 + lsw * 16;
            const void* g = Bbase + (size_t)r * F_ + k0 + lu * 8;
            asm volatile("cp.async.cg.shared.global [%0], [%1], 16;" :: "r"(d), "l"(g));
        }
        asm volatile("cp.async.commit_group;" ::: "memory");
    };

    // ldmatrix lane mappings
    // A (matrices: rows0-7/kh0, rows8-15/kh0, rows0-7/kh1, rows8-15/kh1):
    const int ar  = l & 15;          // row within m16
    const int akh = l >> 4;          // k-half
    // B (matrices: n0-7/kh0, n0-7/kh1, n8-15/kh0, n8-15/kh1):
    const int br  = (l & 7) + ((l >> 4) << 3);
    const int bkh = (l >> 3) & 1;

    float d[4][4][4] = {};

    load_stage(0, 0);
    load_stage(1, KCH);

    for (int s = 0; s < 16; s++) {
        if (s < 14) asm volatile("cp.async.wait_group 1;" ::: "memory");
        else        asm volatile("cp.async.wait_group 0;" ::: "memory");
        __syncthreads();

        const uint32_t as_ = sb + (uint32_t)(s % NSTG) * STG_B;
        const uint32_t bs_ = as_ + 16384;

        #pragma unroll
        for (int kk = 0; kk < 4; kk++) {
            uint32_t bfr[2][4];
            #pragma unroll
            for (int j = 0; j < 2; j++) {
                const int n = wn * 32 + j * 16 + br;
                const uint32_t addr = bs_ + n * 128 + (((kk * 2 + bkh) ^ (n & 7)) * 16);
                asm volatile("ldmatrix.sync.aligned.m8n8.x4.shared.b16 {%0,%1,%2,%3}, [%4];"
                    : "=r"(bfr[j][0]), "=r"(bfr[j][1]), "=r"(bfr[j][2]), "=r"(bfr[j][3])
                    : "r"(addr));
            }
            #pragma unroll
            for (int i = 0; i < 4; i++) {
                const int r = wm * 64 + i * 16 + ar;
                const uint32_t addr = as_ + r * 128 + (((kk * 2 + akh) ^ (r & 7)) * 16);
                uint32_t a0, a1, a2, a3;
                asm volatile("ldmatrix.sync.aligned.m8n8.x4.shared.b16 {%0,%1,%2,%3}, [%4];"
                    : "=r"(a0), "=r"(a1), "=r"(a2), "=r"(a3) : "r"(addr));
                #pragma unroll
                for (int j8 = 0; j8 < 4; j8++) {
                    float* dd = d[i][j8];
                    const uint32_t b0 = bfr[j8 >> 1][(j8 & 1) * 2];
                    const uint32_t b1 = bfr[j8 >> 1][(j8 & 1) * 2 + 1];
                    asm volatile(
                        "mma.sync.aligned.m16n8k16.row.col.f32.bf16.bf16.f32 "
                        "{%0,%1,%2,%3}, {%4,%5,%6,%7}, {%8,%9}, {%0,%1,%2,%3};"
                        : "+f"(dd[0]), "+f"(dd[1]), "+f"(dd[2]), "+f"(dd[3])
                        : "r"(a0), "r"(a1), "r"(a2), "r"(a3), "r"(b0), "r"(b1));
                }
            }
        }
        __syncthreads();
        if (s + 2 < 16) load_stage((s + 2) % NSTG, (s + 2) * KCH);
    }

    // Epilogue: lane l covers rows (l>>2, +8), cols 2*(l&3), +1 per m16n8 tile
    #pragma unroll
    for (int i = 0; i < 4; i++) {
        const int rr = row0 + wm * 64 + i * 16 + (l >> 2);
        #pragma unroll
        for (int j8 = 0; j8 < 4; j8++) {
            const int cc = n0 + wn * 32 + j8 * 8 + 2 * (l & 3);
            *(float2*)(g_logits + (size_t)rr * V_ + cc) =
                make_float2(d[i][j8][0], d[i][j8][1]);
            *(float2*)(g_logits + (size_t)(rr + 8) * V_ + cc) =
                make_float2(d[i][j8][2], d[i][j8][3]);
        }
    }
}

// ---------------------------------------------------------------------------
// Bias + log-softmax + mask (DRAM-roofline-bound; validated R1)
// ---------------------------------------------------------------------------
__global__ void __launch_bounds__(256) softmax_mask_kernel(
    const float* __restrict__ bfc,
    const int* __restrict__ enc_lens, const int* __restrict__ dec_lens,
    float* __restrict__ out)
{
    __shared__ float sbias[V_];
    for (int i = threadIdx.x; i < V_; i += 256) sbias[i] = bfc[i];
    __syncthreads();

    const int warp = threadIdx.x >> 5;
    const int lane = threadIdx.x & 31;
    const int row  = blockIdx.x * 8 + warp;

    const int b  = row >> 14;
    const int tt = (row >> 6) & (T_ - 1);
    const int u  = row & (U_ - 1);

    const float4* lrow = (const float4*)(g_logits + (size_t)row * V_);
    float4*       orow = (float4*)(out + (size_t)row * V_);

    const bool ok = (tt < enc_lens[b]) && (u < dec_lens[b]);
    if (!ok) {
        float4 z = make_float4(0.f, 0.f, 0.f, 0.f);
        #pragma unroll
        for (int j = 0; j < 8; j++) orow[j*32 + lane] = z;
        return;
    }

    float v[32];
    float mx = -CUDART_INF_F;
    #pragma unroll
    for (int j = 0; j < 8; j++) {
        float4 x  = lrow[j*32 + lane];
        float4 bb = ((const float4*)sbias)[j*32 + lane];
        x.x += bb.x; x.y += bb.y; x.z += bb.z; x.w += bb.w;
        v[j*4+0] = x.x; v[j*4+1] = x.y; v[j*4+2] = x.z; v[j*4+3] = x.w;
        mx = fmaxf(mx, fmaxf(fmaxf(x.x, x.y), fmaxf(x.z, x.w)));
    }
    #pragma unroll
    for (int o = 16; o > 0; o >>= 1)
        mx = fmaxf(mx, __shfl_xor_sync(0xFFFFFFFFu, mx, o));

    float s = 0.f;
    #pragma unroll
    for (int i = 0; i < 32; i++) s += __expf(v[i] - mx);
    #pragma unroll
    for (int o = 16; o > 0; o >>= 1)
        s += __shfl_xor_sync(0xFFFFFFFFu, s, o);

    const float lse = mx + logf(s);

    #pragma unroll
    for (int j = 0; j < 8; j++) {
        float4 y;
        y.x = v[j*4+0] - lse; y.y = v[j*4+1] - lse;
        y.z = v[j*4+2] - lse; y.w = v[j*4+3] - lse;
        orow[j*32 + lane] = y;
    }
}

// ---------------------------------------------------------------------------
extern "C" void kernel_launch(void* const* d_in, const int* in_sizes, int n_in,
                              void* d_out, int out_size)
{
    const float* enc      = (const float*)d_in[0];
    const float* dec      = (const float*)d_in[1];
    const float* W_enc    = (const float*)d_in[2];
    const float* b_enc    = (const float*)d_in[3];
    const float* W_dec    = (const float*)d_in[4];
    const float* b_dec    = (const float*)d_in[5];
    const float* W_fc     = (const float*)d_in[6];
    const float* b_fc     = (const float*)d_in[7];
    const int*   enc_lens = (const int*)d_in[8];
    const int*   dec_lens = (const int*)d_in[9];
    float* out = (float*)d_out;
    (void)in_sizes; (void)n_in; (void)out_size;

    cudaFuncSetAttribute(joint_gemm_mma,
                         cudaFuncAttributeMaxDynamicSharedMemorySize, SMEM_GEMM);

    // pe = enc @ W_enc + b_enc   (M = 1024)
    proj_kernel<<<dim3(F_/64, (B_*T_)/64), 256>>>(enc, W_enc, b_enc, 0);
    // pd = dec @ W_dec + b_dec   (M = 256)
    proj_kernel<<<dim3(F_/64, (B_*U_)/64), 256>>>(dec, W_dec, b_dec, 1);
    // WT = bf16(Wfc^T)
    transpose_w<<<dim3(32, 32), 256>>>(W_fc);
    // A = bf16(tanh(pe (+) pd))
    build_A<<<B_*T_, 256>>>();
    // logits = A @ WT^T  (mma.sync bf16)
    joint_gemm_mma<<<dim3(V_/128, ROWS_/128), 256, SMEM_GEMM>>>();
    // out = log_softmax(logits + b_fc) with length masking
    softmax_mask_kernel<<<ROWS_/8, 256>>>(b_fc, enc_lens, dec_lens, out);
}